// round 6
// baseline (speedup 1.0000x reference)
#include <cuda_runtime.h>
#include <math.h>

#define BB   64
#define TT   512
#define II   64
#define HH   512
#define OO   64
#define TGTN 96

#define NCTA 128
#define NTHR 512

// ---- SMEM layout (floats) ----
#define RST   520                 // stage row stride for K=512 (conflict-tuned, 16B aligned)
#define RSX   68                  // stage row stride for K=64
#define OFF_ST0   0               // 16 rows x 520 = 8320
#define OFF_ST1   8320
#define OFF_GP    16640           // 4 planes x (16 cols x 65) = 4160
#define OFF_B0    (OFF_GP + 4160)
#define OFF_B1    (OFF_B0 + 16)
#define OFF_C0    (OFF_B1 + 16)   // 256
#define OFF_C1    (OFF_C0 + 256)  // 256
#define OFF_FC    (OFF_C1 + 256)  // 256
#define SMEM_FLOATS (OFF_FC + 256)
#define SMEM_BYTES  (SMEM_FLOATS * 4)

// ---- device globals (no allocation allowed) ----
__device__ float g_hs0[(size_t)TT * BB * HH];
__device__ float g_h1buf[2 * BB * HH];
__device__ float g_h0buf[2 * BB * HH];
__device__ float g_y[BB * OO];
__device__ unsigned g_bar_count;
__device__ unsigned g_bar_gen;

// ---- grid barrier (128 co-resident CTAs) ----
__device__ __forceinline__ void grid_barrier() {
    __syncthreads();
    if (threadIdx.x == 0) {
        __threadfence();
        volatile unsigned* vgen = &g_bar_gen;
        unsigned old = *vgen;
        unsigned arr = atomicAdd(&g_bar_count, 1u);
        if (arr == NCTA - 1) {
            g_bar_count = 0;
            __threadfence();
            atomicExch(&g_bar_gen, old + 1u);
        } else {
            while (*vgen == old) { }
        }
        __threadfence();
    }
    __syncthreads();
}

// ---- packed fp32x2 FMA ----
__device__ __forceinline__ void fma2(unsigned long long& d, unsigned long long a,
                                     unsigned long long b) {
    asm("fma.rn.f32x2 %0, %1, %2, %0;" : "+l"(d) : "l"(a), "l"(b));
}
__device__ __forceinline__ float acc_sum(unsigned long long a) {
    float lo = __uint_as_float((unsigned)(a & 0xffffffffull));
    float hi = __uint_as_float((unsigned)(a >> 32));
    return lo + hi;
}

// ---- cp.async helpers ----
__device__ __forceinline__ void cp16(float* sdst, const float* gsrc) {
    unsigned s = (unsigned)__cvta_generic_to_shared(sdst);
    asm volatile("cp.async.cg.shared.global [%0], [%1], 16;" :: "r"(s), "l"(gsrc));
}
__device__ __forceinline__ void cp_commit() {
    asm volatile("cp.async.commit_group;" ::: "memory");
}
__device__ __forceinline__ void cp_wait0() {
    asm volatile("cp.async.wait_group 0;" ::: "memory");
}

// ---- 16-wide butterfly reduce: 16 values over 16-lane group (ksub);
//      result for value index k lands on the lane with ksub==k ----
__device__ __forceinline__ float butterfly16(float v[16], int ksub) {
#pragma unroll
    for (int o = 8; o >= 1; o >>= 1) {
#pragma unroll
        for (int i = 0; i < o; i++) {
            float a = v[i], b = v[i + o];
            float send = (ksub & o) ? a : b;
            float recv = __shfl_xor_sync(0xffffffffu, send, o);
            v[i] = ((ksub & o) ? b : a) + recv;
        }
    }
    return v[0];
}

// ---- register weight slice: 4 cols x (2 float4) = 16 u64 ----
// lane's K indices (within kq quarter): {ksub*4..+4} and {64+ksub*4..+4}
__device__ __forceinline__ void load_wreg(unsigned long long W[16],
                                          const float* __restrict__ Wmat,
                                          int cta, int cg, int kq, int ksub) {
#pragma unroll
    for (int c = 0; c < 4; c++) {
        int ng = cg * 4 + c;
        int n  = (ng >> 2) * HH + cta * 4 + (ng & 3);
        const float* base = Wmat + (size_t)n * HH + kq * 128;
        ulonglong2 a  = *(const ulonglong2*)(base + ksub * 4);
        ulonglong2 b2 = *(const ulonglong2*)(base + 64 + ksub * 4);
        W[c * 4 + 0] = a.x;  W[c * 4 + 1] = a.y;
        W[c * 4 + 2] = b2.x; W[c * 4 + 3] = b2.y;
    }
}

__device__ __forceinline__ void load_wx(float wv[4], const float* __restrict__ Wmat,
                                        int cta, int cg, int kq, int ksub) {
#pragma unroll
    for (int c = 0; c < 4; c++) {
        int ng = cg * 4 + c;
        int n  = (ng >> 2) * HH + cta * 4 + (ng & 3);
        wv[c] = Wmat[(size_t)n * II + kq * 16 + ksub];
    }
}

// ---- K=512 GEMM: accumulate gate partials into plane kq of sGp ----
__device__ __forceinline__ void gemm512(
    const float* __restrict__ src, int rstride,
    const unsigned long long W[16], float* sm, int add,
    int cg, int kq, int ksub, int bsub)
{
    float* st0 = sm + OFF_ST0;
    float* st1 = sm + OFF_ST1;
    float* sGp = sm + OFF_GP + kq * 1040;
    const int tid = threadIdx.x;

    // prefetch chunk 0 (16 batches x 512 floats)
#pragma unroll
    for (int i = 0; i < 4; i++) {
        int flat = tid + i * NTHR;            // 0..2047
        int r = flat >> 7, seg = flat & 127;
        cp16(st0 + r * RST + seg * 4, src + (size_t)r * rstride + seg * 4);
    }
    cp_commit();

#pragma unroll 1
    for (int ch = 0; ch < 4; ch++) {
        cp_wait0();
        __syncthreads();
        if (ch < 3) {
            float* nb = ((ch + 1) & 1) ? st1 : st0;
#pragma unroll
            for (int i = 0; i < 4; i++) {
                int flat = tid + i * NTHR;
                int r = flat >> 7, seg = flat & 127;
                cp16(nb + r * RST + seg * 4,
                     src + (size_t)(16 * (ch + 1) + r) * rstride + seg * 4);
            }
            cp_commit();
        }
        const float* S = (ch & 1) ? st1 : st0;
#pragma unroll
        for (int ph = 0; ph < 2; ph++) {
            unsigned long long acc[16];
#pragma unroll
            for (int i = 0; i < 16; i++) acc[i] = 0ull;
#pragma unroll
            for (int bbi = 0; bbi < 4; bbi++) {
                int r = ph * 8 + bbi * 2 + bsub;
                const float* row = S + r * RST + kq * 128;
                ulonglong2 ha = *(const ulonglong2*)(row + ksub * 4);
                ulonglong2 hb = *(const ulonglong2*)(row + 64 + ksub * 4);
#pragma unroll
                for (int c = 0; c < 4; c++) {
                    unsigned long long* a = &acc[c * 4 + bbi];
                    fma2(*a, ha.x, W[c * 4 + 0]);
                    fma2(*a, ha.y, W[c * 4 + 1]);
                    fma2(*a, hb.x, W[c * 4 + 2]);
                    fma2(*a, hb.y, W[c * 4 + 3]);
                }
            }
            float v[16];
#pragma unroll
            for (int i = 0; i < 16; i++) v[i] = acc_sum(acc[i]);
            float red = butterfly16(v, ksub);
            int col = cg * 4 + (ksub >> 2);
            int b   = ch * 16 + ph * 8 + (ksub & 3) * 2 + bsub;
            float* dst = &sGp[col * 65 + b];
            if (add) *dst += red; else *dst = red;
        }
    }
}

// ---- K=64 GEMM (x / y inputs) ----
__device__ __forceinline__ void gemm64(
    const float* __restrict__ src, int rstride,
    const float wv[4], float* sm, int add,
    int cg, int kq, int ksub, int bsub)
{
    float* st  = sm + OFF_ST0;
    float* sGp = sm + OFF_GP + kq * 1040;
    const int tid = threadIdx.x;
#pragma unroll
    for (int i = 0; i < 2; i++) {
        int flat = tid + i * NTHR;           // 0..1023
        int r = flat >> 4, seg = flat & 15;
        cp16(st + r * RSX + seg * 4, src + (size_t)r * rstride + seg * 4);
    }
    cp_commit();
    cp_wait0();
    __syncthreads();
#pragma unroll
    for (int ph = 0; ph < 8; ph++) {
        float v[16];
#pragma unroll
        for (int bbi = 0; bbi < 4; bbi++) {
            int r = ph * 8 + bbi * 2 + bsub;
            float h = st[r * RSX + kq * 16 + ksub];
#pragma unroll
            for (int c = 0; c < 4; c++) v[c * 4 + bbi] = wv[c] * h;
        }
        float red = butterfly16(v, ksub);
        int col = cg * 4 + (ksub >> 2);
        int b   = ph * 8 + (ksub & 3) * 2 + bsub;
        float* dst = &sGp[col * 65 + b];
        if (add) *dst += red; else *dst = red;
    }
    __syncthreads();   // stage buffer reused by following gemm512 prefetch
}

// ---- LSTM elementwise: sums the 4 kq planes; tid<256 active ----
__device__ __forceinline__ void lstm_elem(float* sm, const float* sB,
                                          float* sC, float* __restrict__ dsth,
                                          int cta) {
    int u = threadIdx.x;
    if (u < 256) {
        int b = u >> 2, jj = u & 3;
        float g[4];
#pragma unroll
        for (int gt = 0; gt < 4; gt++) {
            float s = sB[gt * 4 + jj];
#pragma unroll
            for (int p = 0; p < 4; p++)
                s += sm[OFF_GP + p * 1040 + (gt * 4 + jj) * 65 + b];
            g[gt] = s;
        }
        float c  = sC[u];
        float si = 1.f / (1.f + expf(-g[0]));
        float sf = 1.f / (1.f + expf(-g[1]));
        float so = 1.f / (1.f + expf(-g[3]));
        float cn = sf * c + si * tanhf(g[2]);
        float hn = so * tanhf(cn);
        sC[u] = cn;
        dsth[b * HH + cta * 4 + jj] = hn;
    }
}

// ---- persistent kernel ----
extern "C" __global__ void __launch_bounds__(NTHR, 1)
lstm_persistent_kernel(
    const float* __restrict__ x,
    const float* __restrict__ Wih0, const float* __restrict__ Whh0,
    const float* __restrict__ bih0, const float* __restrict__ bhh0,
    const float* __restrict__ Wih1, const float* __restrict__ Whh1,
    const float* __restrict__ bih1, const float* __restrict__ bhh1,
    const float* __restrict__ Wfc,  const float* __restrict__ bfc,
    float* __restrict__ out)
{
    extern __shared__ float sm[];
    const int cta  = blockIdx.x;
    const int tid  = threadIdx.x;
    const int lane = tid & 31;
    const int wid  = tid >> 5;      // 0..15
    const int cg   = wid >> 2;      // 0..3 : 4 gate cols each
    const int kq   = wid & 3;       // 0..3 : K quarter
    const int ksub = lane & 15;     // K sub-slice within quarter
    const int bsub = lane >> 4;     // batch parity

    if (tid < 16) {
        int n = (tid >> 2) * HH + cta * 4 + (tid & 3);
        sm[OFF_B0 + tid] = bih0[n] + bhh0[n];
        sm[OFF_B1 + tid] = bih1[n] + bhh1[n];
    }
    if (tid < 256) {
        sm[OFF_C0 + tid] = 0.f;
        sm[OFF_C1 + tid] = 0.f;
    }
    __syncthreads();

    // ================= encoder layer 0 =================
    {
        unsigned long long WH0[16];
        load_wreg(WH0, Whh0, cta, cg, kq, ksub);
        float wx0[4];
        load_wx(wx0, Wih0, cta, cg, kq, ksub);
        for (int t = 0; t < TT; t++) {
            gemm64(x + (size_t)t * II, TT * II, wx0, sm, 0, cg, kq, ksub, bsub);
            if (t > 0)
                gemm512(g_hs0 + (size_t)(t - 1) * BB * HH, HH, WH0, sm, 1,
                        cg, kq, ksub, bsub);
            __syncthreads();
            lstm_elem(sm, sm + OFF_B0, sm + OFF_C0,
                      g_hs0 + (size_t)t * BB * HH, cta);
            grid_barrier();
        }
    }

    // ================= encoder layer 1 =================
    {
        unsigned long long Wi1[16], Wh1[16];
        load_wreg(Wi1, Wih1, cta, cg, kq, ksub);
        load_wreg(Wh1, Whh1, cta, cg, kq, ksub);
        for (int t = 0; t < TT; t++) {
            gemm512(g_hs0 + (size_t)t * BB * HH, HH, Wi1, sm, 0, cg, kq, ksub, bsub);
            if (t > 0)
                gemm512(g_h1buf + (size_t)((t - 1) & 1) * BB * HH, HH, Wh1, sm, 1,
                        cg, kq, ksub, bsub);
            __syncthreads();
            lstm_elem(sm, sm + OFF_B1, sm + OFF_C1,
                      g_h1buf + (size_t)(t & 1) * BB * HH, cta);
            grid_barrier();
        }
    }

    // ================= decoder =================
    for (int s = 0; s < TGTN; s++) {
        // phase A : layer-0 cell
        {
            float wx0[4];
            load_wx(wx0, Wih0, cta, cg, kq, ksub);
            unsigned long long Wa[16];
            load_wreg(Wa, Whh0, cta, cg, kq, ksub);
            const float* xin = (s == 0) ? (x + (size_t)(TT - 1) * II) : g_y;
            int xs = (s == 0) ? (TT * II) : OO;
            gemm64(xin, xs, wx0, sm, 0, cg, kq, ksub, bsub);
            const float* hp = (s == 0) ? (g_hs0 + (size_t)(TT - 1) * BB * HH)
                                       : (g_h0buf + (size_t)((s - 1) & 1) * BB * HH);
            gemm512(hp, HH, Wa, sm, 1, cg, kq, ksub, bsub);
            __syncthreads();
            lstm_elem(sm, sm + OFF_B0, sm + OFF_C0,
                      g_h0buf + (size_t)(s & 1) * BB * HH, cta);
            grid_barrier();
        }
        // phase B : layer-1 cell
        {
            unsigned long long Wb[16];
            load_wreg(Wb, Wih1, cta, cg, kq, ksub);
            gemm512(g_h0buf + (size_t)(s & 1) * BB * HH, HH, Wb, sm, 0,
                    cg, kq, ksub, bsub);
            load_wreg(Wb, Whh1, cta, cg, kq, ksub);
            const float* hp = (s == 0) ? (g_h1buf + (size_t)BB * HH)
                                       : (g_h1buf + (size_t)((s - 1) & 1) * BB * HH);
            gemm512(hp, HH, Wb, sm, 1, cg, kq, ksub, bsub);
            __syncthreads();
            lstm_elem(sm, sm + OFF_B1, sm + OFF_C1,
                      g_h1buf + (size_t)(s & 1) * BB * HH, cta);
            grid_barrier();
        }
        // phase C : y = h1 @ Wfc^T + bfc
        {
            float* sFc = sm + OFF_FC;
            const float* h1 = g_h1buf + (size_t)(s & 1) * BB * HH;
            if (tid < 256) {
                int p = tid >> 3, q = tid & 7;     // 32 outputs/CTA, 8-way K split
                int flat = cta * 32 + p;           // 4096 = 64 b x 64 o
                int bb = flat >> 6, oo = flat & 63;
                const float4* h4 = (const float4*)(h1 + (size_t)bb * HH + q * 64);
                const float4* w4 = (const float4*)(Wfc + (size_t)oo * HH + q * 64);
                float sum = 0.f;
#pragma unroll
                for (int k = 0; k < 16; k++) {
                    float4 a = h4[k], w = w4[k];
                    sum += a.x * w.x + a.y * w.y + a.z * w.z + a.w * w.w;
                }
                sFc[p * 8 + q] = sum;
            }
            __syncthreads();
            if (tid < 32) {
                int fl = cta * 32 + tid;
                int bb2 = fl >> 6, oo2 = fl & 63;
                float tot = bfc[oo2];
#pragma unroll
                for (int j = 0; j < 8; j++) tot += sFc[tid * 8 + j];
                g_y[bb2 * OO + oo2] = tot;
                out[(size_t)bb2 * TGTN * OO + (size_t)s * OO + oo2] = tot;
            }
            grid_barrier();
        }
    }
}

// ---- host launch ----
extern "C" void kernel_launch(void* const* d_in, const int* in_sizes, int n_in,
                              void* d_out, int out_size) {
    (void)in_sizes; (void)n_in; (void)out_size;
    const float* x    = (const float*)d_in[0];
    const float* Wih0 = (const float*)d_in[1];
    const float* Whh0 = (const float*)d_in[2];
    const float* bih0 = (const float*)d_in[3];
    const float* bhh0 = (const float*)d_in[4];
    const float* Wih1 = (const float*)d_in[5];
    const float* Whh1 = (const float*)d_in[6];
    const float* bih1 = (const float*)d_in[7];
    const float* bhh1 = (const float*)d_in[8];
    const float* Wfc  = (const float*)d_in[9];
    const float* bfc  = (const float*)d_in[10];

    cudaFuncSetAttribute(lstm_persistent_kernel,
                         cudaFuncAttributeMaxDynamicSharedMemorySize, SMEM_BYTES);
    lstm_persistent_kernel<<<NCTA, NTHR, SMEM_BYTES>>>(
        x, Wih0, Whh0, bih0, bhh0, Wih1, Whh1, bih1, bhh1, Wfc, bfc,
        (float*)d_out);
}

// round 7
// speedup vs baseline: 1.7105x; 1.7105x over previous
#include <cuda_runtime.h>
#include <math.h>

#define BB   64
#define TT   512
#define II   64
#define HH   512
#define OO   64
#define TGTN 96

#define NCTA 128
#define NTHR 256

// ---- SMEM layout (floats) ----
#define OFF_ST0   0                   // stage buf 0: 16 batches x 512 = 8192
#define OFF_ST1   8192                // stage buf 1: 8192
#define OFF_GP0   16384               // gate partials K-half 0: 16*65 = 1040
#define OFF_GP1   (OFF_GP0 + 1040)
#define OFF_B0    (OFF_GP1 + 1040)
#define OFF_B1    (OFF_B0 + 16)
#define OFF_C0    (OFF_B1 + 16)       // 256
#define OFF_C1    (OFF_C0 + 256)      // 256
#define OFF_FC    (OFF_C1 + 256)      // 256
#define SMEM_FLOATS (OFF_FC + 256)
#define SMEM_BYTES  (SMEM_FLOATS * 4)

// ---- device globals (no allocation allowed) ----
__device__ float g_hs0[(size_t)TT * BB * HH];  // layer-0 output history
__device__ float g_h1buf[2 * BB * HH];
__device__ float g_h0buf[2 * BB * HH];
__device__ float g_y[BB * OO];
__device__ unsigned g_bar_count;
__device__ unsigned g_bar_gen;

// ---- grid barrier (128 co-resident CTAs) ----
__device__ __forceinline__ void grid_barrier() {
    __syncthreads();
    if (threadIdx.x == 0) {
        __threadfence();
        volatile unsigned* vgen = &g_bar_gen;
        unsigned old = *vgen;
        unsigned arr = atomicAdd(&g_bar_count, 1u);
        if (arr == NCTA - 1) {
            g_bar_count = 0;
            __threadfence();
            atomicExch(&g_bar_gen, old + 1u);
        } else {
            while (*vgen == old) { }
        }
        __threadfence();
    }
    __syncthreads();
}

// ---- packed fp32x2 FMA ----
__device__ __forceinline__ void fma2(unsigned long long& d, unsigned long long a,
                                     unsigned long long b) {
    asm("fma.rn.f32x2 %0, %1, %2, %0;" : "+l"(d) : "l"(a), "l"(b));
}
__device__ __forceinline__ float acc_sum(unsigned long long a) {
    float lo = __uint_as_float((unsigned)(a & 0xffffffffull));
    float hi = __uint_as_float((unsigned)(a >> 32));
    return lo + hi;
}

// ---- cp.async helpers ----
__device__ __forceinline__ void cp16(float* sdst, const float* gsrc) {
    unsigned s = (unsigned)__cvta_generic_to_shared(sdst);
    asm volatile("cp.async.cg.shared.global [%0], [%1], 16;" :: "r"(s), "l"(gsrc));
}
__device__ __forceinline__ void cp_commit() {
    asm volatile("cp.async.commit_group;" ::: "memory");
}
__device__ __forceinline__ void cp_wait0() {
    asm volatile("cp.async.wait_group 0;" ::: "memory");
}

// ---- register-resident weight slice: 4 cols x 8 K-floats = 16 u64 ----
// lane K indices (within kh half of 256): {lane*4..+4} and {128+lane*4..+4}
// -> 16B lane stride, conflict-free LDS.128 on the matching h reads.
struct WReg { unsigned long long w[16]; };

__device__ __forceinline__ void load_wreg(WReg& W, const float* __restrict__ Wmat,
                                          int cta, int cg, int kh, int lane) {
#pragma unroll
    for (int c = 0; c < 4; c++) {
        int ng = cg * 4 + c;
        int n  = (ng >> 2) * HH + cta * 4 + (ng & 3);
        const float* base = Wmat + (size_t)n * HH + kh * 256;
        ulonglong2 a  = *(const ulonglong2*)(base + lane * 4);
        ulonglong2 b2 = *(const ulonglong2*)(base + 128 + lane * 4);
        W.w[c * 4 + 0] = a.x;  W.w[c * 4 + 1] = a.y;
        W.w[c * 4 + 2] = b2.x; W.w[c * 4 + 3] = b2.y;
    }
}

__device__ __forceinline__ void load_wx(float wv[4], const float* __restrict__ Wmat,
                                        int cta, int cg, int kh, int lane) {
#pragma unroll
    for (int c = 0; c < 4; c++) {
        int ng = cg * 4 + c;
        int n  = (ng >> 2) * HH + cta * 4 + (ng & 3);
        wv[c] = Wmat[(size_t)n * II + kh * 32 + lane];
    }
}

// ---- butterfly reduce of 32 per-lane partials (index c*8+bb) across lanes;
//      result for index l lands on lane l ----
__device__ __forceinline__ float butterfly32(float v[32], int lane) {
#pragma unroll
    for (int o = 16; o >= 1; o >>= 1) {
#pragma unroll
        for (int i = 0; i < o; i++) {
            float a = v[i], b = v[i + o];
            float send = (lane & o) ? a : b;
            float recv = __shfl_xor_sync(0xffffffffu, send, o);
            v[i] = ((lane & o) ? b : a) + recv;
        }
    }
    return v[0];
}

// ---- K=512 GEMM: gate_pre[16 cols x 64 b] partials into sGp[kh] ----
__device__ __forceinline__ void gemm512(
    const float* __restrict__ src, int rstride,   // src[b][k]
    const WReg& W, float* sm, int add,
    int cg, int kh, int lane)
{
    float* st0 = sm + OFF_ST0;
    float* st1 = sm + OFF_ST1;
    float* sGp = sm + (kh ? OFF_GP1 : OFF_GP0);
    const int tid = threadIdx.x;

    // prefetch chunk 0 (16 batches x 512 floats)
#pragma unroll
    for (int i = 0; i < 8; i++) {
        int flat = tid + i * NTHR;           // 0..2047
        int b = flat >> 7, seg = flat & 127; // 128 x 16B per row
        cp16(st0 + b * 512 + seg * 4, src + (size_t)b * rstride + seg * 4);
    }
    cp_commit();

#pragma unroll 1
    for (int ch = 0; ch < 4; ch++) {
        cp_wait0();
        __syncthreads();
        if (ch < 3) {
            float* nb = ((ch + 1) & 1) ? st1 : st0;
#pragma unroll
            for (int i = 0; i < 8; i++) {
                int flat = tid + i * NTHR;
                int b = flat >> 7, seg = flat & 127;
                cp16(nb + b * 512 + seg * 4,
                     src + (size_t)(16 * (ch + 1) + b) * rstride + seg * 4);
            }
            cp_commit();
        }
        const float* S = (ch & 1) ? st1 : st0;
#pragma unroll
        for (int g = 0; g < 2; g++) {
            unsigned long long acc2[32];
#pragma unroll
            for (int i = 0; i < 32; i++) acc2[i] = 0ull;
#pragma unroll
            for (int bb = 0; bb < 8; bb++) {
                const float* row = S + (g * 8 + bb) * 512 + kh * 256;
                ulonglong2 ha = *(const ulonglong2*)(row + lane * 4);
                ulonglong2 hb = *(const ulonglong2*)(row + 128 + lane * 4);
#pragma unroll
                for (int c = 0; c < 4; c++) {
                    unsigned long long* a = &acc2[c * 8 + bb];
                    fma2(*a, ha.x, W.w[c * 4 + 0]);
                    fma2(*a, ha.y, W.w[c * 4 + 1]);
                    fma2(*a, hb.x, W.w[c * 4 + 2]);
                    fma2(*a, hb.y, W.w[c * 4 + 3]);
                }
            }
            float v[32];
#pragma unroll
            for (int i = 0; i < 32; i++) v[i] = acc_sum(acc2[i]);
            float r = butterfly32(v, lane);
            int ngOut = cg * 4 + (lane >> 3);
            int bOut  = ch * 16 + g * 8 + (lane & 7);
            float* dst = &sGp[ngOut * 65 + bOut];
            if (add) *dst += r; else *dst = r;
        }
    }
}

// ---- K=64 GEMM (x / y inputs) ----
__device__ __forceinline__ void gemm64(
    const float* __restrict__ src, int rstride,
    const float wv[4], float* sm, int add,
    int cg, int kh, int lane)
{
    float* st  = sm + OFF_ST0;
    float* sGp = sm + (kh ? OFF_GP1 : OFF_GP0);
    const int tid = threadIdx.x;
#pragma unroll
    for (int i = 0; i < 4; i++) {
        int flat = tid + i * NTHR;          // 0..1023
        int b = flat >> 4, seg = flat & 15; // 16 x 16B per row
        cp16(st + b * 64 + seg * 4, src + (size_t)b * rstride + seg * 4);
    }
    cp_commit();
    cp_wait0();
    __syncthreads();
#pragma unroll
    for (int g = 0; g < 8; g++) {
        float v[32];
#pragma unroll
        for (int bb = 0; bb < 8; bb++) {
            float h = st[(g * 8 + bb) * 64 + kh * 32 + lane];
#pragma unroll
            for (int c = 0; c < 4; c++) v[c * 8 + bb] = wv[c] * h;
        }
        float r = butterfly32(v, lane);
        int ngOut = cg * 4 + (lane >> 3);
        int bOut  = g * 8 + (lane & 7);
        float* dst = &sGp[ngOut * 65 + bOut];
        if (add) *dst += r; else *dst = r;
    }
    __syncthreads();   // stage buffer reused immediately by following gemm512
}

// ---- LSTM elementwise (CTA-local 4 hidden units) ----
__device__ __forceinline__ void lstm_elem2(const float* sm, const float* sB,
                                           float* sC, float* __restrict__ dsth,
                                           int cta) {
    const float* g0 = sm + OFF_GP0;
    const float* g1 = sm + OFF_GP1;
    int u = threadIdx.x;          // 64 b x 4 jj
    int b = u >> 2, jj = u & 3;
    float gi = g0[(0  + jj) * 65 + b] + g1[(0  + jj) * 65 + b] + sB[0  + jj];
    float gf = g0[(4  + jj) * 65 + b] + g1[(4  + jj) * 65 + b] + sB[4  + jj];
    float gg = g0[(8  + jj) * 65 + b] + g1[(8  + jj) * 65 + b] + sB[8  + jj];
    float go = g0[(12 + jj) * 65 + b] + g1[(12 + jj) * 65 + b] + sB[12 + jj];
    float c  = sC[u];
    float si = 1.f / (1.f + expf(-gi));
    float sf = 1.f / (1.f + expf(-gf));
    float so = 1.f / (1.f + expf(-go));
    float cn = sf * c + si * tanhf(gg);
    float hn = so * tanhf(cn);
    sC[u] = cn;
    dsth[b * HH + cta * 4 + jj] = hn;
}

// ---- persistent kernel ----
extern "C" __global__ void __launch_bounds__(NTHR, 1)
lstm_persistent_kernel(
    const float* __restrict__ x,
    const float* __restrict__ Wih0, const float* __restrict__ Whh0,
    const float* __restrict__ bih0, const float* __restrict__ bhh0,
    const float* __restrict__ Wih1, const float* __restrict__ Whh1,
    const float* __restrict__ bih1, const float* __restrict__ bhh1,
    const float* __restrict__ Wfc,  const float* __restrict__ bfc,
    float* __restrict__ out)
{
    extern __shared__ float sm[];
    const int cta  = blockIdx.x;
    const int tid  = threadIdx.x;
    const int wid  = tid >> 5;
    const int lane = tid & 31;
    const int cg   = wid >> 1;   // 0..3 : column group (4 cols)
    const int kh   = wid & 1;    // K half

    if (tid < 16) {
        int n = (tid >> 2) * HH + cta * 4 + (tid & 3);
        sm[OFF_B0 + tid] = bih0[n] + bhh0[n];
        sm[OFF_B1 + tid] = bih1[n] + bhh1[n];
    }
    sm[OFF_C0 + tid] = 0.f;
    sm[OFF_C1 + tid] = 0.f;
    __syncthreads();

    // ================= encoder layer 0 =================
    {
        WReg WH0;  load_wreg(WH0, Whh0, cta, cg, kh, lane);
        float wx0[4]; load_wx(wx0, Wih0, cta, cg, kh, lane);
        for (int t = 0; t < TT; t++) {
            gemm64(x + (size_t)t * II, TT * II, wx0, sm, 0, cg, kh, lane);
            if (t > 0)
                gemm512(g_hs0 + (size_t)(t - 1) * BB * HH, HH, WH0, sm, 1, cg, kh, lane);
            __syncthreads();
            lstm_elem2(sm, sm + OFF_B0, sm + OFF_C0,
                       g_hs0 + (size_t)t * BB * HH, cta);
            grid_barrier();
        }
    }

    // ================= encoder layer 1 =================
    {
        WReg Wi1;  load_wreg(Wi1, Wih1, cta, cg, kh, lane);
        WReg Wh1;  load_wreg(Wh1, Whh1, cta, cg, kh, lane);
        for (int t = 0; t < TT; t++) {
            gemm512(g_hs0 + (size_t)t * BB * HH, HH, Wi1, sm, 0, cg, kh, lane);
            if (t > 0)
                gemm512(g_h1buf + (size_t)((t - 1) & 1) * BB * HH, HH, Wh1, sm, 1,
                        cg, kh, lane);
            __syncthreads();
            lstm_elem2(sm, sm + OFF_B1, sm + OFF_C1,
                       g_h1buf + (size_t)(t & 1) * BB * HH, cta);
            grid_barrier();
        }
    }

    // ================= decoder =================
    for (int s = 0; s < TGTN; s++) {
        // phase A : layer-0 cell
        {
            float wx0[4]; load_wx(wx0, Wih0, cta, cg, kh, lane);
            WReg Wa; load_wreg(Wa, Whh0, cta, cg, kh, lane);
            const float* xin = (s == 0) ? (x + (size_t)(TT - 1) * II) : g_y;
            int xs = (s == 0) ? (TT * II) : OO;
            gemm64(xin, xs, wx0, sm, 0, cg, kh, lane);
            const float* hp = (s == 0) ? (g_hs0 + (size_t)(TT - 1) * BB * HH)
                                       : (g_h0buf + (size_t)((s - 1) & 1) * BB * HH);
            gemm512(hp, HH, Wa, sm, 1, cg, kh, lane);
            __syncthreads();
            lstm_elem2(sm, sm + OFF_B0, sm + OFF_C0,
                       g_h0buf + (size_t)(s & 1) * BB * HH, cta);
            grid_barrier();
        }
        // phase B : layer-1 cell
        {
            WReg Wb; load_wreg(Wb, Wih1, cta, cg, kh, lane);
            gemm512(g_h0buf + (size_t)(s & 1) * BB * HH, HH, Wb, sm, 0, cg, kh, lane);
            load_wreg(Wb, Whh1, cta, cg, kh, lane);
            const float* hp = (s == 0) ? (g_h1buf + (size_t)BB * HH)
                                       : (g_h1buf + (size_t)((s - 1) & 1) * BB * HH);
            gemm512(hp, HH, Wb, sm, 1, cg, kh, lane);
            __syncthreads();
            lstm_elem2(sm, sm + OFF_B1, sm + OFF_C1,
                       g_h1buf + (size_t)(s & 1) * BB * HH, cta);
            grid_barrier();
        }
        // phase C : y = h1 @ Wfc^T + bfc
        {
            float* sFc = sm + OFF_FC;
            const float* h1 = g_h1buf + (size_t)(s & 1) * BB * HH;
            int p = tid >> 3, q = tid & 7;        // 32 outputs/CTA, 8-way K split
            int flat = cta * 32 + p;              // 4096 = 64 b x 64 o
            int bb = flat >> 6, oo = flat & 63;
            const float4* h4 = (const float4*)(h1 + (size_t)bb * HH + q * 64);
            const float4* w4 = (const float4*)(Wfc + (size_t)oo * HH + q * 64);
            float sum = 0.f;
#pragma unroll
            for (int k = 0; k < 16; k++) {
                float4 a = h4[k], w = w4[k];
                sum += a.x * w.x + a.y * w.y + a.z * w.z + a.w * w.w;
            }
            sFc[p * 8 + q] = sum;
            __syncthreads();
            if (tid < 32) {
                int fl = cta * 32 + tid;
                int bb2 = fl >> 6, oo2 = fl & 63;
                float tot = bfc[oo2];
#pragma unroll
                for (int j = 0; j < 8; j++) tot += sFc[tid * 8 + j];
                g_y[bb2 * OO + oo2] = tot;
                out[(size_t)bb2 * TGTN * OO + (size_t)s * OO + oo2] = tot;
            }
            grid_barrier();
        }
    }
}

// ---- host launch ----
extern "C" void kernel_launch(void* const* d_in, const int* in_sizes, int n_in,
                              void* d_out, int out_size) {
    (void)in_sizes; (void)n_in; (void)out_size;
    const float* x    = (const float*)d_in[0];
    const float* Wih0 = (const float*)d_in[1];
    const float* Whh0 = (const float*)d_in[2];
    const float* bih0 = (const float*)d_in[3];
    const float* bhh0 = (const float*)d_in[4];
    const float* Wih1 = (const float*)d_in[5];
    const float* Whh1 = (const float*)d_in[6];
    const float* bih1 = (const float*)d_in[7];
    const float* bhh1 = (const float*)d_in[8];
    const float* Wfc  = (const float*)d_in[9];
    const float* bfc  = (const float*)d_in[10];

    cudaFuncSetAttribute(lstm_persistent_kernel,
                         cudaFuncAttributeMaxDynamicSharedMemorySize, SMEM_BYTES);
    lstm_persistent_kernel<<<NCTA, NTHR, SMEM_BYTES>>>(
        x, Wih0, Whh0, bih0, bhh0, Wih1, Whh1, bih1, bhh1, Wfc, bfc,
        (float*)d_out);
}